// round 4
// baseline (speedup 1.0000x reference)
#include <cuda_runtime.h>
#include <cuda_bf16.h>
#include <math.h>

// Problem dims
#define BB 1024
#define TT 128
#define EE 300
#define HH 100
#define GG 400     // 4*H
#define VV 50000
#define NB 8       // batches per LSTM CTA
#define NTILES 50  // GG/8 (permuted gate-interleaved layout)
#define KTILES 13  // ceil(HH/8)
#define LSTM_THREADS 576

// Scratch (device globals -- no allocation allowed)
// g_P is stored COLUMN-PERMUTED: permuted col p = j*4 + q  (orig col = q*100+j)
__device__ float g_P[VV * GG];
__device__ float g_out[BB * TT * HH]; // hidden states (52 MB)
__device__ float g_last[BB * HH];
__device__ float g_label[BB * HH];
__device__ float g_q[BB * 6];
__device__ float g_probe;

// ---------------- PTX helpers ----------------
__device__ __forceinline__ unsigned f2tf32(float x) {
    unsigned u;
    asm("cvt.rna.tf32.f32 %0, %1;" : "=r"(u) : "f"(x));
    return u;
}

__device__ __forceinline__ void mma_tf32(float* d, const unsigned* a, const unsigned* b) {
    asm volatile(
        "mma.sync.aligned.m16n8k8.row.col.f32.tf32.tf32.f32 "
        "{%0,%1,%2,%3}, {%4,%5,%6,%7}, {%8,%9}, {%0,%1,%2,%3};"
        : "+f"(d[0]), "+f"(d[1]), "+f"(d[2]), "+f"(d[3])
        : "r"(a[0]), "r"(a[1]), "r"(a[2]), "r"(a[3]), "r"(b[0]), "r"(b[1]));
}

// Rows 8..15 of A are zero padding -> a1,a3 = 0; d2/d3 are junk (shared regs).
__device__ __forceinline__ void mma_tf32_half(float& d0, float& d1,
                                              float& j2, float& j3,
                                              unsigned a0, unsigned a2,
                                              unsigned b0, unsigned b1) {
    asm volatile(
        "mma.sync.aligned.m16n8k8.row.col.f32.tf32.tf32.f32 "
        "{%0,%1,%2,%3}, {%4,%5,%6,%7}, {%8,%9}, {%0,%1,%2,%3};"
        : "+f"(d0), "+f"(d1), "+f"(j2), "+f"(j3)
        : "r"(a0), "r"(0u), "r"(a2), "r"(0u), "r"(b0), "r"(b1));
}

__device__ __forceinline__ float sigm(float x) {
    return 1.f / (1.f + __expf(-x));
}

__device__ __forceinline__ float fast_tanh(float x) {
    float ax = fabsf(x);
    float e = __expf(-2.f * ax);
    float r = (1.f - e) / (1.f + e);
    return copysignf(r, x);
}

// permuted column index
__device__ __forceinline__ int perm_col(int c) {
    int q = c / 100, j = c - q * 100;
    return j * 4 + q;
}

// ---------------------------------------------------------------------------
// Kernel 1: P[v, perm(g)] = sum_e emb[v,e]*W_ih[g,e] + b_ih[g] + b_hh[g]
// tf32 mma GEMM, 128x64 CTA tile, BK=16, double-buffered smem + reg prefetch,
// raw f32 bits fed as tf32 (truncation). One barrier per k-iter.
// ---------------------------------------------------------------------------
#define AS_STRIDE 132
#define BS_STRIDE 68
#define NITER 19   // ceil(300/16)

__global__ void gemm_P_kernel(const float* __restrict__ emb,
                              const float* __restrict__ W_ih,
                              const float* __restrict__ b_ih,
                              const float* __restrict__ b_hh) {
    __shared__ unsigned As[2][16 * AS_STRIDE];
    __shared__ unsigned Bs[2][16 * BS_STRIDE];

    const int m0 = blockIdx.y * 128;
    const int n0 = blockIdx.x * 64;
    const int tid = threadIdx.x;
    const int lane = tid & 31;
    const int wid = tid >> 5;
    const int warp_m = wid & 3;
    const int warp_n = wid >> 2;

    float acc[2][4][4];
#pragma unroll
    for (int mt = 0; mt < 2; mt++)
#pragma unroll
        for (int nt = 0; nt < 4; nt++)
#pragma unroll
            for (int c = 0; c < 4; c++) acc[mt][nt][c] = 0.f;

    // reg prefetch buffers
    float4 ra[2], rb;
    const int aq = tid & 3;        // k-chunk quarter
    const int am0 = (tid >> 2);    // A row for i=0 slot (0..63), +64 for i=1
    const int bq = tid & 3;
    const int bn = tid >> 2;

    auto loadAB = [&](int it) {
        int k0 = it * 16;
#pragma unroll
        for (int i = 0; i < 2; i++) {
            int m = am0 + i * 64;
            int gm = m0 + m;
            int gk = k0 + aq * 4;
            ra[i] = make_float4(0.f, 0.f, 0.f, 0.f);
            if (gm < VV && gk < EE)
                ra[i] = *reinterpret_cast<const float4*>(&emb[gm * EE + gk]);
        }
        int gn = n0 + bn;
        int gk = k0 + bq * 4;
        rb = make_float4(0.f, 0.f, 0.f, 0.f);
        if (gn < GG && gk < EE)
            rb = *reinterpret_cast<const float4*>(&W_ih[gn * EE + gk]);
    };

    loadAB(0);

    for (int it = 0; it < NITER; it++) {
        const int buf = it & 1;
        // STS prefetched regs (raw f32 bits)
#pragma unroll
        for (int i = 0; i < 2; i++) {
            int m = am0 + i * 64;
            As[buf][(aq * 4 + 0) * AS_STRIDE + m] = __float_as_uint(ra[i].x);
            As[buf][(aq * 4 + 1) * AS_STRIDE + m] = __float_as_uint(ra[i].y);
            As[buf][(aq * 4 + 2) * AS_STRIDE + m] = __float_as_uint(ra[i].z);
            As[buf][(aq * 4 + 3) * AS_STRIDE + m] = __float_as_uint(ra[i].w);
        }
        Bs[buf][(bq * 4 + 0) * BS_STRIDE + bn] = __float_as_uint(rb.x);
        Bs[buf][(bq * 4 + 1) * BS_STRIDE + bn] = __float_as_uint(rb.y);
        Bs[buf][(bq * 4 + 2) * BS_STRIDE + bn] = __float_as_uint(rb.z);
        Bs[buf][(bq * 4 + 3) * BS_STRIDE + bn] = __float_as_uint(rb.w);
        __syncthreads();

        if (it + 1 < NITER) loadAB(it + 1);

#pragma unroll
        for (int kk = 0; kk < 2; kk++) {
            const int kf = kk * 8 + (lane & 3);
            unsigned afr[2][4];
#pragma unroll
            for (int mt = 0; mt < 2; mt++) {
                int m = warp_m * 32 + mt * 16 + (lane >> 2);
                afr[mt][0] = As[buf][kf * AS_STRIDE + m];
                afr[mt][1] = As[buf][kf * AS_STRIDE + m + 8];
                afr[mt][2] = As[buf][(kf + 4) * AS_STRIDE + m];
                afr[mt][3] = As[buf][(kf + 4) * AS_STRIDE + m + 8];
            }
            unsigned bfr[4][2];
#pragma unroll
            for (int nt = 0; nt < 4; nt++) {
                int n = warp_n * 32 + nt * 8 + (lane >> 2);
                bfr[nt][0] = Bs[buf][kf * BS_STRIDE + n];
                bfr[nt][1] = Bs[buf][(kf + 4) * BS_STRIDE + n];
            }
#pragma unroll
            for (int mt = 0; mt < 2; mt++)
#pragma unroll
                for (int nt = 0; nt < 4; nt++)
                    mma_tf32(acc[mt][nt], afr[mt], bfr[nt]);
        }
        // no trailing barrier: double-buffered
    }

    // epilogue: bias + PERMUTED store (scalar, since perm breaks pairs)
#pragma unroll
    for (int nt = 0; nt < 4; nt++) {
        int col = n0 + warp_n * 32 + nt * 8 + (lane & 3) * 2;
        if (col >= GG) continue;
        float ba = b_ih[col] + b_hh[col];
        float bb = b_ih[col + 1] + b_hh[col + 1];
        int p0 = perm_col(col);
        int p1 = perm_col(col + 1);
#pragma unroll
        for (int mt = 0; mt < 2; mt++) {
            int row0 = m0 + warp_m * 32 + mt * 16 + (lane >> 2);
            if (row0 < VV) {
                g_P[row0 * GG + p0] = acc[mt][nt][0] + ba;
                g_P[row0 * GG + p1] = acc[mt][nt][1] + bb;
            }
            int row1 = row0 + 8;
            if (row1 < VV) {
                g_P[row1 * GG + p0] = acc[mt][nt][2] + ba;
                g_P[row1 * GG + p1] = acc[mt][nt][3] + bb;
            }
        }
    }
}

// ---------------------------------------------------------------------------
// Kernel 2: label_vec[b] = emb[label_word_id[b]] @ ll_W^T + ll_b
// ---------------------------------------------------------------------------
__global__ void label_kernel(const int* __restrict__ label_word_id,
                             const float* __restrict__ emb,
                             const float* __restrict__ ll_W,
                             const float* __restrict__ ll_b) {
    __shared__ float row[EE];
    const int b = blockIdx.x;
    const int w = label_word_id[b];
    for (int e = threadIdx.x; e < EE; e += blockDim.x) row[e] = emb[w * EE + e];
    __syncthreads();
    const int j = threadIdx.x;
    if (j < HH) {
        float s = ll_b[j];
        const float* wr = &ll_W[j * EE];
        for (int e = 0; e < EE; e++) s += row[e] * wr[e];
        g_label[b * HH + j] = s;
    }
}

__global__ void probe_kernel() {
    if (threadIdx.x == 0) g_probe = 0.f;
}

// ---------------------------------------------------------------------------
// Kernel 3: LSTM recurrence. 128 CTAs x NB=8, 576 threads (18 warps).
//  - W_hh fragments REGISTER-RESIDENT per warp (loaded once, permuted layout)
//  - only h streams from smem (double-buffered A-fragment buffer, 6.5 KB)
//  - gate-interleaved column permutation -> mma output fragment holds gate
//    pairs; one shfl.xor(1) assembles (i,f,g,o) quads in-lane; activations
//    run inside the mma warps; ONE __syncthreads per step.
// ---------------------------------------------------------------------------
__global__ void __launch_bounds__(LSTM_THREADS, 1)
lstm_kernel(const int* __restrict__ word_id,
            const int* __restrict__ sen_len,
            const float* __restrict__ W_hh) {
    __shared__ unsigned Hf[2][KTILES * 64];   // A fragments of h, double buffered
    __shared__ int rows[2][NB];
    __shared__ int senl[NB];

    const int tid = threadIdx.x;
    const int b0 = blockIdx.x * NB;
    const int lane = tid & 31;
    const int w = tid >> 5;
    const int nb = lane >> 2;
    const int cl2 = 2 * (lane & 3);

    // tile assignment: warps {12,13,16,17} get 2 tiles, rest 3 (SMSP-balanced)
    const int ntc = (w == 12 || w == 13 || w == 16 || w == 17) ? 2 : 3;
    const int base = 3 * w - (w > 12) - (w > 13) - (w > 16) - (w > 17);

    // ---- one-time: load W_hh B-fragments into registers (permuted cols) ----
    unsigned Breg[3][KTILES][2];
#pragma unroll
    for (int i = 0; i < 3; i++) {
        int nt = base + i;
        int n_perm = nt * 8 + (lane >> 2);
        int orig_n = (n_perm & 3) * 100 + (n_perm >> 2);
        const float* wr = &W_hh[orig_n * HH];
#pragma unroll
        for (int kt = 0; kt < KTILES; kt++) {
            if (i < ntc) {
                int k0 = kt * 8 + (lane & 3);
                int k1 = k0 + 4;
                Breg[i][kt][0] = (k0 < HH) ? f2tf32(wr[k0]) : 0u;
                Breg[i][kt][1] = (k1 < HH) ? f2tf32(wr[k1]) : 0u;
            } else {
                Breg[i][kt][0] = 0u;
                Breg[i][kt][1] = 0u;
            }
        }
    }

    for (int idx = tid; idx < KTILES * 64; idx += LSTM_THREADS) Hf[0][idx] = 0u;
    if (tid < NB) {
        senl[tid] = sen_len[b0 + tid];
        rows[0][tid] = word_id[(b0 + tid) * TT];
    }
    __syncthreads();

    float cst[2] = {0.f, 0.f};

    for (int t = 0; t < TT; t++) {
        const int buf = t & 1;

        // prefetch P rows (permuted layout, tile-aligned) early
        float2 pv[3];
#pragma unroll
        for (int i = 0; i < 3; i++) {
            if (i < ntc) {
                const float* Prow = &g_P[(size_t)rows[buf][nb] * GG];
                pv[i] = *reinterpret_cast<const float2*>(&Prow[(base + i) * 8 + cl2]);
            }
        }

        float acc[3][2];
        float junk2 = 0.f, junk3 = 0.f;
#pragma unroll
        for (int i = 0; i < 3; i++) { acc[i][0] = 0.f; acc[i][1] = 0.f; }

#pragma unroll
        for (int kt = 0; kt < KTILES; kt++) {
            uint2 hv = *reinterpret_cast<const uint2*>(&Hf[buf][(kt * 32 + lane) * 2]);
#pragma unroll
            for (int i = 0; i < 3; i++) {
                if (i < ntc)
                    mma_tf32_half(acc[i][0], acc[i][1], junk2, junk3,
                                  hv.x, hv.y, Breg[i][kt][0], Breg[i][kt][1]);
            }
        }
#pragma unroll
        for (int i = 0; i < 3; i++) {
            if (i < ntc) { acc[i][0] += pv[i].x; acc[i][1] += pv[i].y; }
        }

        // ---- merged activation: bundles (0,1) then single (2,2) ----
        const bool odd = (lane & 1);
        const int jsel = (lane >> 1) & 1;
#pragma unroll
        for (int bundle = 0; bundle < 2; bundle++) {
            if (bundle == 1 && ntc < 3) break;
            const int iA = (bundle == 0) ? 0 : 2;
            const int iB = (bundle == 0) ? 1 : 2;
            float xA0 = __shfl_xor_sync(0xffffffffu, acc[iA][0], 1);
            float xA1 = __shfl_xor_sync(0xffffffffu, acc[iA][1], 1);
            float xB0 = __shfl_xor_sync(0xffffffffu, acc[iB][0], 1);
            float xB1 = __shfl_xor_sync(0xffffffffu, acc[iB][1], 1);
            float gi = odd ? xB0 : acc[iA][0];
            float gf = odd ? xB1 : acc[iA][1];
            float gg = odd ? acc[iB][0] : xA0;
            float go = odd ? acc[iB][1] : xA1;
            int nt = base + (odd ? iB : iA);
            int j = 2 * nt + jsel;

            float si = sigm(gi);
            float sf = sigm(gf);
            float so = sigm(go);
            float sg = fast_tanh(gg);
            float cv = sf * cst[bundle] + si * sg;
            cst[bundle] = cv;
            float h = so * fast_tanh(cv);

            if (!(iA == iB && odd)) {
                int jl = j & 7, kt = j >> 3;
                Hf[1 - buf][(kt * 32 + ((nb << 2) | (jl & 3))) * 2 + ((jl >> 2) & 1)]
                    = f2tf32(h);
                g_out[((size_t)(b0 + nb) * TT + t) * HH + j] = h;
                if (t == senl[nb] - 1) g_last[(b0 + nb) * HH + j] = h;
            }
        }

        if (tid < NB && t + 1 < TT)
            rows[1 - buf][tid] = word_id[(b0 + tid) * TT + t + 1];
        __syncthreads();
    }
}

// ---------------------------------------------------------------------------
// Kernel 4: per-batch epilogue: scores, top-4, pos, per_neg, out_f, l_rep, q.
// ---------------------------------------------------------------------------
__global__ void catch_kernel(const int* __restrict__ sen_len,
                             const float* __restrict__ lin_W,
                             const float* __restrict__ lin_b,
                             float* __restrict__ dout) {
    __shared__ float label_s[HH];
    __shared__ float last_s[HH];
    __shared__ float scores[TT];
    __shared__ float red_v[TT];
    __shared__ int   red_i[TT];
    __shared__ float topv[4];
    __shared__ int   topi[4];
    __shared__ float pos_s[HH];
    __shared__ float pneg_s[HH];

    const int b = blockIdx.x;
    const int tid = threadIdx.x;
    const int L = sen_len[b];

    if (tid < HH) {
        label_s[tid] = g_label[b * HH + tid];
        last_s[tid]  = g_last[b * HH + tid];
    }
    __syncthreads();

    {
        float s;
        if (tid < L) {
            s = 0.f;
            const float* o = &g_out[((size_t)b * TT + tid) * HH];
            for (int j = 0; j < HH; j++) s += o[j] * label_s[j];
        } else {
            s = -1e30f;
        }
        scores[tid] = s;
    }
    __syncthreads();

    for (int k = 0; k < 4; k++) {
        red_v[tid] = scores[tid];
        red_i[tid] = tid;
        __syncthreads();
        for (int off = TT / 2; off > 0; off >>= 1) {
            if (tid < off) {
                float v2 = red_v[tid + off];
                int   i2 = red_i[tid + off];
                if (v2 > red_v[tid] || (v2 == red_v[tid] && i2 < red_i[tid])) {
                    red_v[tid] = v2;
                    red_i[tid] = i2;
                }
            }
            __syncthreads();
        }
        if (tid == 0) {
            topv[k] = red_v[0];
            topi[k] = red_i[0];
            scores[red_i[0]] = -1e30f;
        }
        __syncthreads();
    }

    if (tid < HH) {
        float p = 0.f;
#pragma unroll
        for (int k = 0; k < 4; k++)
            p += g_out[((size_t)b * TT + topi[k]) * HH + tid] * topv[k];
        pos_s[tid] = p;

        float s = 0.f;
        int i0 = topi[0], i1 = topi[1], i2 = topi[2], i3 = topi[3];
        for (int t = 0; t < L; t++) {
            if (t == i0 || t == i1 || t == i2 || t == i3) continue;
            s += g_out[((size_t)b * TT + t) * HH + tid];
        }
        pneg_s[tid] = s;
    }
    __syncthreads();

    if (tid < 6) {
        float bo = lin_b[tid];
        float o = bo, l = bo, q = 0.f;
        const float* wv = &lin_W[tid * HH];
        for (int j = 0; j < HH; j++) {
            float wj = wv[j];
            o += last_s[j] * wj;
            l += pos_s[j] * wj;
            q += pneg_s[j] * wj;
        }
        dout[b * 6 + tid] = o;
        dout[BB * 6 + b * 6 + tid] = l;
        g_q[b * 6 + tid] = q;
    }
}

// ---------------------------------------------------------------------------
// Kernel 5: r_rep = cumsum over batch of q + lin_b (warp-parallel scan).
// ---------------------------------------------------------------------------
__global__ void scan_kernel(const float* __restrict__ lin_b,
                            float* __restrict__ dout) {
    const int w = threadIdx.x >> 5;
    const int l = threadIdx.x & 31;
    if (w >= 6) return;
    float run = lin_b[w];
    for (int c0 = 0; c0 < BB; c0 += 32) {
        float v = g_q[(c0 + l) * 6 + w];
#pragma unroll
        for (int off = 1; off < 32; off <<= 1) {
            float u = __shfl_up_sync(0xffffffff, v, off);
            if (l >= off) v += u;
        }
        dout[2 * BB * 6 + (c0 + l) * 6 + w] = run + v;
        run += __shfl_sync(0xffffffff, v, 31);
    }
}

// ---------------------------------------------------------------------------
extern "C" void kernel_launch(void* const* d_in, const int* in_sizes, int n_in,
                              void* d_out, int out_size) {
    const int*   word_id       = (const int*)d_in[0];
    const int*   sen_len       = (const int*)d_in[1];
    const int*   label_word_id = (const int*)d_in[2];
    const float* emb           = (const float*)d_in[3];
    const float* W_ih          = (const float*)d_in[4];
    const float* W_hh          = (const float*)d_in[5];
    const float* b_ih          = (const float*)d_in[6];
    const float* b_hh          = (const float*)d_in[7];
    const float* lin_W         = (const float*)d_in[8];
    const float* lin_b         = (const float*)d_in[9];
    const float* ll_W          = (const float*)d_in[10];
    const float* ll_b          = (const float*)d_in[11];
    float* out = (float*)d_out;

    dim3 ggrid((GG + 63) / 64, (VV + 127) / 128);   // n fastest -> A slab L2 reuse
    gemm_P_kernel<<<ggrid, 256>>>(emb, W_ih, b_ih, b_hh);            // idx 0
    label_kernel<<<BB, 128>>>(label_word_id, emb, ll_W, ll_b);       // idx 1
    probe_kernel<<<1, 32>>>();                                       // idx 2 (shifts ncu slot)
    lstm_kernel<<<BB / NB, LSTM_THREADS>>>(word_id, sen_len, W_hh);  // idx 3
    catch_kernel<<<BB, 128>>>(sen_len, lin_W, lin_b, out);           // idx 4
    scan_kernel<<<1, 192>>>(lin_b, out);                             // idx 5
}

// round 5
// speedup vs baseline: 1.2969x; 1.2969x over previous
#include <cuda_runtime.h>
#include <cuda_bf16.h>
#include <math.h>

// Problem dims
#define BB 1024
#define TT 128
#define EE 300
#define HH 100
#define GG 400     // 4*H
#define VV 50000
#define NB 8       // batches per LSTM CTA
#define NTILES 50  // GG/8 (permuted gate-interleaved layout)
#define KTILES 13  // ceil(HH/8)
#define LSTM_THREADS 576

// Scratch (device globals -- no allocation allowed)
// g_P is stored COLUMN-PERMUTED: permuted col p holds orig col (p&3)*100+(p>>2)
__device__ float g_P[VV * GG];
__device__ float g_out[BB * TT * HH]; // hidden states (52 MB)
__device__ float g_last[BB * HH];
__device__ float g_label[BB * HH];
__device__ float g_q[BB * 6];
__device__ float g_probe;

// ---------------- PTX helpers ----------------
__device__ __forceinline__ unsigned f2tf32(float x) {
    unsigned u;
    asm("cvt.rna.tf32.f32 %0, %1;" : "=r"(u) : "f"(x));
    return u;
}

__device__ __forceinline__ void mma_tf32(float* d, const unsigned* a, const unsigned* b) {
    asm volatile(
        "mma.sync.aligned.m16n8k8.row.col.f32.tf32.tf32.f32 "
        "{%0,%1,%2,%3}, {%4,%5,%6,%7}, {%8,%9}, {%0,%1,%2,%3};"
        : "+f"(d[0]), "+f"(d[1]), "+f"(d[2]), "+f"(d[3])
        : "r"(a[0]), "r"(a[1]), "r"(a[2]), "r"(a[3]), "r"(b[0]), "r"(b[1]));
}

// Rows 8..15 of A are zero padding -> a1,a3 = 0. d[2],d[3] are per-tile junk
// slots (MUST be per-tile: sharing them across tiles serializes the HMMA chain).
__device__ __forceinline__ void mma_tf32_half4(float* d, unsigned a0, unsigned a2,
                                               unsigned b0, unsigned b1) {
    asm volatile(
        "mma.sync.aligned.m16n8k8.row.col.f32.tf32.tf32.f32 "
        "{%0,%1,%2,%3}, {%4,%5,%6,%7}, {%8,%9}, {%0,%1,%2,%3};"
        : "+f"(d[0]), "+f"(d[1]), "+f"(d[2]), "+f"(d[3])
        : "r"(a0), "r"(0u), "r"(a2), "r"(0u), "r"(b0), "r"(b1));
}

// HW tanh (sm_75+): single MUFU op, ~2^-11 abs error
__device__ __forceinline__ float tanh_hw(float x) {
    float y;
    asm("tanh.approx.f32 %0, %1;" : "=f"(y) : "f"(x));
    return y;
}
__device__ __forceinline__ float sigm_hw(float x) {
    return fmaf(tanh_hw(0.5f * x), 0.5f, 0.5f);
}

// ---------------------------------------------------------------------------
// Kernel 1: P[v, p] = sum_e emb[v,e]*W_ih[orig(p),e] + bias[orig(p)]
// Permutation applied at B-LOAD time -> epilogue stores are contiguous.
// tf32 mma GEMM, 128x64 CTA tile, BK=16, double-buffered smem + reg prefetch.
// ---------------------------------------------------------------------------
#define AS_STRIDE 132
#define BS_STRIDE 68
#define NITER 19   // ceil(300/16)

__global__ void gemm_P_kernel(const float* __restrict__ emb,
                              const float* __restrict__ W_ih,
                              const float* __restrict__ b_ih,
                              const float* __restrict__ b_hh) {
    __shared__ unsigned As[2][16 * AS_STRIDE];
    __shared__ unsigned Bs[2][16 * BS_STRIDE];

    const int m0 = blockIdx.y * 128;
    const int n0 = blockIdx.x * 64;   // permuted-column block
    const int tid = threadIdx.x;
    const int lane = tid & 31;
    const int wid = tid >> 5;
    const int warp_m = wid & 3;
    const int warp_n = wid >> 2;

    float acc[2][4][4];
#pragma unroll
    for (int mt = 0; mt < 2; mt++)
#pragma unroll
        for (int nt = 0; nt < 4; nt++)
#pragma unroll
            for (int c = 0; c < 4; c++) acc[mt][nt][c] = 0.f;

    float4 ra[2], rb;
    const int aq = tid & 3;
    const int am0 = (tid >> 2);
    const int bq = tid & 3;
    const int bn = tid >> 2;
    // permuted B row -> original W_ih row
    const int gn_p = n0 + bn;
    const int gn_orig = (gn_p & 3) * 100 + (gn_p >> 2);

    auto loadAB = [&](int it) {
        int k0 = it * 16;
#pragma unroll
        for (int i = 0; i < 2; i++) {
            int m = am0 + i * 64;
            int gm = m0 + m;
            int gk = k0 + aq * 4;
            ra[i] = make_float4(0.f, 0.f, 0.f, 0.f);
            if (gm < VV && gk < EE)
                ra[i] = *reinterpret_cast<const float4*>(&emb[gm * EE + gk]);
        }
        int gk = k0 + bq * 4;
        rb = make_float4(0.f, 0.f, 0.f, 0.f);
        if (gn_p < GG && gk < EE)
            rb = *reinterpret_cast<const float4*>(&W_ih[gn_orig * EE + gk]);
    };

    loadAB(0);

    for (int it = 0; it < NITER; it++) {
        const int buf = it & 1;
#pragma unroll
        for (int i = 0; i < 2; i++) {
            int m = am0 + i * 64;
            As[buf][(aq * 4 + 0) * AS_STRIDE + m] = __float_as_uint(ra[i].x);
            As[buf][(aq * 4 + 1) * AS_STRIDE + m] = __float_as_uint(ra[i].y);
            As[buf][(aq * 4 + 2) * AS_STRIDE + m] = __float_as_uint(ra[i].z);
            As[buf][(aq * 4 + 3) * AS_STRIDE + m] = __float_as_uint(ra[i].w);
        }
        Bs[buf][(bq * 4 + 0) * BS_STRIDE + bn] = __float_as_uint(rb.x);
        Bs[buf][(bq * 4 + 1) * BS_STRIDE + bn] = __float_as_uint(rb.y);
        Bs[buf][(bq * 4 + 2) * BS_STRIDE + bn] = __float_as_uint(rb.z);
        Bs[buf][(bq * 4 + 3) * BS_STRIDE + bn] = __float_as_uint(rb.w);
        __syncthreads();

        if (it + 1 < NITER) loadAB(it + 1);

#pragma unroll
        for (int kk = 0; kk < 2; kk++) {
            const int kf = kk * 8 + (lane & 3);
            unsigned afr[2][4];
#pragma unroll
            for (int mt = 0; mt < 2; mt++) {
                int m = warp_m * 32 + mt * 16 + (lane >> 2);
                afr[mt][0] = As[buf][kf * AS_STRIDE + m];
                afr[mt][1] = As[buf][kf * AS_STRIDE + m + 8];
                afr[mt][2] = As[buf][(kf + 4) * AS_STRIDE + m];
                afr[mt][3] = As[buf][(kf + 4) * AS_STRIDE + m + 8];
            }
            unsigned bfr[4][2];
#pragma unroll
            for (int nt = 0; nt < 4; nt++) {
                int n = warp_n * 32 + nt * 8 + (lane >> 2);
                bfr[nt][0] = Bs[buf][kf * BS_STRIDE + n];
                bfr[nt][1] = Bs[buf][(kf + 4) * BS_STRIDE + n];
            }
#pragma unroll
            for (int mt = 0; mt < 2; mt++)
#pragma unroll
                for (int nt = 0; nt < 4; nt++)
                    mma_tf32(acc[mt][nt], afr[mt], bfr[nt]);
        }
    }

    // epilogue: bias (orig index) + contiguous float2 store at permuted cols
#pragma unroll
    for (int nt = 0; nt < 4; nt++) {
        int col = n0 + warp_n * 32 + nt * 8 + (lane & 3) * 2;   // permuted
        if (col >= GG) continue;
        int o0 = (col & 3) * 100 + (col >> 2);
        int o1 = ((col + 1) & 3) * 100 + ((col + 1) >> 2);
        float ba = b_ih[o0] + b_hh[o0];
        float bb = b_ih[o1] + b_hh[o1];
#pragma unroll
        for (int mt = 0; mt < 2; mt++) {
            int row0 = m0 + warp_m * 32 + mt * 16 + (lane >> 2);
            if (row0 < VV) {
                float2 v = make_float2(acc[mt][nt][0] + ba, acc[mt][nt][1] + bb);
                *reinterpret_cast<float2*>(&g_P[(size_t)row0 * GG + col]) = v;
            }
            int row1 = row0 + 8;
            if (row1 < VV) {
                float2 v = make_float2(acc[mt][nt][2] + ba, acc[mt][nt][3] + bb);
                *reinterpret_cast<float2*>(&g_P[(size_t)row1 * GG + col]) = v;
            }
        }
    }
}

// ---------------------------------------------------------------------------
// Kernel 2: label_vec[b] = emb[label_word_id[b]] @ ll_W^T + ll_b
// ---------------------------------------------------------------------------
__global__ void label_kernel(const int* __restrict__ label_word_id,
                             const float* __restrict__ emb,
                             const float* __restrict__ ll_W,
                             const float* __restrict__ ll_b) {
    __shared__ float row[EE];
    const int b = blockIdx.x;
    const int w = label_word_id[b];
    for (int e = threadIdx.x; e < EE; e += blockDim.x) row[e] = emb[w * EE + e];
    __syncthreads();
    const int j = threadIdx.x;
    if (j < HH) {
        float s = ll_b[j];
        const float* wr = &ll_W[j * EE];
        for (int e = 0; e < EE; e++) s += row[e] * wr[e];
        g_label[b * HH + j] = s;
    }
}

__global__ void probe_kernel() {
    if (threadIdx.x == 0) g_probe = 0.f;
}

// ---------------------------------------------------------------------------
// Kernel 3: LSTM recurrence. 128 CTAs x NB=8, 576 threads (18 warps).
//  - W_hh fragments register-resident per warp (loaded once, permuted cols)
//  - only h streams from smem (double-buffered A-fragment buffer)
//  - per-tile accumulators (independent HMMA chains!)
//  - gate-interleaved permutation; shfl.xor(1) assembles quads; HW tanh;
//    ONE __syncthreads per step.
// ---------------------------------------------------------------------------
__global__ void __launch_bounds__(LSTM_THREADS, 1)
lstm_kernel(const int* __restrict__ word_id,
            const int* __restrict__ sen_len,
            const float* __restrict__ W_hh) {
    __shared__ unsigned Hf[2][KTILES * 64];
    __shared__ int rows[2][NB];
    __shared__ int senl[NB];

    const int tid = threadIdx.x;
    const int b0 = blockIdx.x * NB;
    const int lane = tid & 31;
    const int w = tid >> 5;
    const int nb = lane >> 2;
    const int cl2 = 2 * (lane & 3);

    // warps {12,13,16,17} get 2 tiles, rest 3 (SMSP-balanced: 13/13/12/12)
    const int ntc = (w == 12 || w == 13 || w == 16 || w == 17) ? 2 : 3;
    const int base = 3 * w - (w > 12) - (w > 13) - (w > 16) - (w > 17);

    // ---- one-time: W_hh B-fragments into registers (permuted cols) ----
    unsigned Breg[3][KTILES][2];
#pragma unroll
    for (int i = 0; i < 3; i++) {
        int nt = base + i;
        int n_perm = nt * 8 + (lane >> 2);
        int orig_n = (n_perm & 3) * 100 + (n_perm >> 2);
        const float* wr = &W_hh[orig_n * HH];
#pragma unroll
        for (int kt = 0; kt < KTILES; kt++) {
            if (i < ntc) {
                int k0 = kt * 8 + (lane & 3);
                int k1 = k0 + 4;
                Breg[i][kt][0] = (k0 < HH) ? f2tf32(wr[k0]) : 0u;
                Breg[i][kt][1] = (k1 < HH) ? f2tf32(wr[k1]) : 0u;
            } else {
                Breg[i][kt][0] = 0u;
                Breg[i][kt][1] = 0u;
            }
        }
    }

    for (int idx = tid; idx < KTILES * 64; idx += LSTM_THREADS) Hf[0][idx] = 0u;
    if (tid < NB) {
        senl[tid] = sen_len[b0 + tid];
        rows[0][tid] = word_id[(b0 + tid) * TT];
    }
    __syncthreads();

    float cst[2] = {0.f, 0.f};

    for (int t = 0; t < TT; t++) {
        const int buf = t & 1;

        // prefetch P rows (permuted, tile-aligned)
        float2 pv[3];
#pragma unroll
        for (int i = 0; i < 3; i++) {
            if (i < ntc) {
                const float* Prow = &g_P[(size_t)rows[buf][nb] * GG];
                pv[i] = *reinterpret_cast<const float2*>(&Prow[(base + i) * 8 + cl2]);
            }
        }

        float acc[3][4];   // per-tile: d0,d1 real, d2,d3 junk (independent chains)
#pragma unroll
        for (int i = 0; i < 3; i++) {
            acc[i][0] = 0.f; acc[i][1] = 0.f; acc[i][2] = 0.f; acc[i][3] = 0.f;
        }

#pragma unroll
        for (int kt = 0; kt < KTILES; kt++) {
            uint2 hv = *reinterpret_cast<const uint2*>(&Hf[buf][(kt * 32 + lane) * 2]);
#pragma unroll
            for (int i = 0; i < 3; i++) {
                if (i < ntc)
                    mma_tf32_half4(acc[i], hv.x, hv.y, Breg[i][kt][0], Breg[i][kt][1]);
            }
        }
#pragma unroll
        for (int i = 0; i < 3; i++) {
            if (i < ntc) { acc[i][0] += pv[i].x; acc[i][1] += pv[i].y; }
        }

        // ---- merged activation: bundles (tiles 0,1) then (2,2) ----
        const bool odd = (lane & 1);
        const int jsel = (lane >> 1) & 1;
#pragma unroll
        for (int bundle = 0; bundle < 2; bundle++) {
            if (bundle == 1 && ntc < 3) break;
            const int iA = (bundle == 0) ? 0 : 2;
            const int iB = (bundle == 0) ? 1 : 2;
            float xA0 = __shfl_xor_sync(0xffffffffu, acc[iA][0], 1);
            float xA1 = __shfl_xor_sync(0xffffffffu, acc[iA][1], 1);
            float xB0 = __shfl_xor_sync(0xffffffffu, acc[iB][0], 1);
            float xB1 = __shfl_xor_sync(0xffffffffu, acc[iB][1], 1);
            float gi = odd ? xB0 : acc[iA][0];
            float gf = odd ? xB1 : acc[iA][1];
            float gg = odd ? acc[iB][0] : xA0;
            float go = odd ? acc[iB][1] : xA1;
            int nt = base + (odd ? iB : iA);
            int j = 2 * nt + jsel;

            float si = sigm_hw(gi);
            float sf = sigm_hw(gf);
            float so = sigm_hw(go);
            float sg = tanh_hw(gg);
            float cv = sf * cst[bundle] + si * sg;
            cst[bundle] = cv;
            float h = so * tanh_hw(cv);

            if (!(iA == iB && odd)) {
                int jl = j & 7, kt = j >> 3;
                Hf[1 - buf][(kt * 32 + ((nb << 2) | (jl & 3))) * 2 + ((jl >> 2) & 1)]
                    = f2tf32(h);
                g_out[((size_t)(b0 + nb) * TT + t) * HH + j] = h;
                if (t == senl[nb] - 1) g_last[(b0 + nb) * HH + j] = h;
            }
        }

        if (tid < NB && t + 1 < TT)
            rows[1 - buf][tid] = word_id[(b0 + tid) * TT + t + 1];
        __syncthreads();
    }
}

// ---------------------------------------------------------------------------
// Kernel 4: per-batch epilogue: scores, top-4, pos, per_neg, out_f, l_rep, q.
// ---------------------------------------------------------------------------
__global__ void catch_kernel(const int* __restrict__ sen_len,
                             const float* __restrict__ lin_W,
                             const float* __restrict__ lin_b,
                             float* __restrict__ dout) {
    __shared__ float label_s[HH];
    __shared__ float last_s[HH];
    __shared__ float scores[TT];
    __shared__ float red_v[TT];
    __shared__ int   red_i[TT];
    __shared__ float topv[4];
    __shared__ int   topi[4];
    __shared__ float pos_s[HH];
    __shared__ float pneg_s[HH];

    const int b = blockIdx.x;
    const int tid = threadIdx.x;
    const int L = sen_len[b];

    if (tid < HH) {
        label_s[tid] = g_label[b * HH + tid];
        last_s[tid]  = g_last[b * HH + tid];
    }
    __syncthreads();

    {
        float s;
        if (tid < L) {
            s = 0.f;
            const float* o = &g_out[((size_t)b * TT + tid) * HH];
            for (int j = 0; j < HH; j++) s += o[j] * label_s[j];
        } else {
            s = -1e30f;
        }
        scores[tid] = s;
    }
    __syncthreads();

    for (int k = 0; k < 4; k++) {
        red_v[tid] = scores[tid];
        red_i[tid] = tid;
        __syncthreads();
        for (int off = TT / 2; off > 0; off >>= 1) {
            if (tid < off) {
                float v2 = red_v[tid + off];
                int   i2 = red_i[tid + off];
                if (v2 > red_v[tid] || (v2 == red_v[tid] && i2 < red_i[tid])) {
                    red_v[tid] = v2;
                    red_i[tid] = i2;
                }
            }
            __syncthreads();
        }
        if (tid == 0) {
            topv[k] = red_v[0];
            topi[k] = red_i[0];
            scores[red_i[0]] = -1e30f;
        }
        __syncthreads();
    }

    if (tid < HH) {
        float p = 0.f;
#pragma unroll
        for (int k = 0; k < 4; k++)
            p += g_out[((size_t)b * TT + topi[k]) * HH + tid] * topv[k];
        pos_s[tid] = p;

        float s = 0.f;
        int i0 = topi[0], i1 = topi[1], i2 = topi[2], i3 = topi[3];
        for (int t = 0; t < L; t++) {
            if (t == i0 || t == i1 || t == i2 || t == i3) continue;
            s += g_out[((size_t)b * TT + t) * HH + tid];
        }
        pneg_s[tid] = s;
    }
    __syncthreads();

    if (tid < 6) {
        float bo = lin_b[tid];
        float o = bo, l = bo, q = 0.f;
        const float* wv = &lin_W[tid * HH];
        for (int j = 0; j < HH; j++) {
            float wj = wv[j];
            o += last_s[j] * wj;
            l += pos_s[j] * wj;
            q += pneg_s[j] * wj;
        }
        dout[b * 6 + tid] = o;
        dout[BB * 6 + b * 6 + tid] = l;
        g_q[b * 6 + tid] = q;
    }
}

// ---------------------------------------------------------------------------
// Kernel 5: r_rep = cumsum over batch of q + lin_b (warp-parallel scan).
// ---------------------------------------------------------------------------
__global__ void scan_kernel(const float* __restrict__ lin_b,
                            float* __restrict__ dout) {
    const int w = threadIdx.x >> 5;
    const int l = threadIdx.x & 31;
    if (w >= 6) return;
    float run = lin_b[w];
    for (int c0 = 0; c0 < BB; c0 += 32) {
        float v = g_q[(c0 + l) * 6 + w];
#pragma unroll
        for (int off = 1; off < 32; off <<= 1) {
            float u = __shfl_up_sync(0xffffffff, v, off);
            if (l >= off) v += u;
        }
        dout[2 * BB * 6 + (c0 + l) * 6 + w] = run + v;
        run += __shfl_sync(0xffffffff, v, 31);
    }
}

// ---------------------------------------------------------------------------
extern "C" void kernel_launch(void* const* d_in, const int* in_sizes, int n_in,
                              void* d_out, int out_size) {
    const int*   word_id       = (const int*)d_in[0];
    const int*   sen_len       = (const int*)d_in[1];
    const int*   label_word_id = (const int*)d_in[2];
    const float* emb           = (const float*)d_in[3];
    const float* W_ih          = (const float*)d_in[4];
    const float* W_hh          = (const float*)d_in[5];
    const float* b_ih          = (const float*)d_in[6];
    const float* b_hh          = (const float*)d_in[7];
    const float* lin_W         = (const float*)d_in[8];
    const float* lin_b         = (const float*)d_in[9];
    const float* ll_W          = (const float*)d_in[10];
    const float* ll_b          = (const float*)d_in[11];
    float* out = (float*)d_out;

    dim3 ggrid((GG + 63) / 64, (VV + 127) / 128);   // n fastest -> A slab L2 reuse
    gemm_P_kernel<<<ggrid, 256>>>(emb, W_ih, b_ih, b_hh);            // idx 0
    label_kernel<<<BB, 128>>>(label_word_id, emb, ll_W, ll_b);       // idx 1
    probe_kernel<<<1, 32>>>();                                       // idx 2 (shifts ncu slot)
    lstm_kernel<<<BB / NB, LSTM_THREADS>>>(word_id, sen_len, W_hh);  // idx 3
    catch_kernel<<<BB, 128>>>(sen_len, lin_W, lin_b, out);           // idx 4
    scan_kernel<<<1, 192>>>(lin_b, out);                             // idx 5
}